// round 3
// baseline (speedup 1.0000x reference)
#include <cuda_runtime.h>
#include <cstdint>
#include <cstddef>

#define NN 100000
#define RR 4
#define EE 300000
#define HH 64
#define SS 4096
#define PP 2

// ------------------------- scratch (static device globals; no allocs) -------------------------
__device__ float g_deg[RR * NN];                 // degree, then in-place inverse degree
__device__ float g_Bcat[(size_t)NN * 128];       // aggregated [B0 | B1] per node
__device__ float g_h1[(size_t)NN * HH];          // layer-1 output
__device__ unsigned char g_isseed[NN];
__device__ float g_sA[SS * 128];                 // Bcat gathered at seeds
__device__ float g_h2[SS * HH];
__device__ float g_hs[SS * HH];
__device__ float g_D1[PP * SS * 256];
__device__ float g_D2[PP * SS * 32];
__device__ float g_F1[PP * SS * 256];
__device__ float g_F2[(size_t)PP * SS * 2048];

// ------------------------- helpers -------------------------
__device__ __forceinline__ void red_add4(float* p, float a, float b, float c, float d) {
    asm volatile("red.global.add.v4.f32 [%0], {%1,%2,%3,%4};" ::
                 "l"(p), "f"(a), "f"(b), "f"(c), "f"(d) : "memory");
}

// ------------------------- small kernels -------------------------
__global__ void k_seedflag(const int* __restrict__ seeds) {
    int i = blockIdx.x * blockDim.x + threadIdx.x;
    if (i < SS) g_isseed[seeds[i]] = 1;
}

__global__ void k_deg(const int* __restrict__ edges) {
    int i = blockIdx.x * blockDim.x + threadIdx.x;
    if (i >= RR * EE) return;
    int r = i / EE;
    int dst = edges[2 * i + 1];
    atomicAdd(&g_deg[r * NN + dst], 1.0f);
}

__global__ void k_invdeg() {
    int i = blockIdx.x * blockDim.x + threadIdx.x;
    if (i < RR * NN) g_deg[i] = 1.0f / fmaxf(g_deg[i], 1.0f);
}

// One warp per edge. lanes 0-15 accumulate basis b=0, lanes 16-31 basis b=1.
// Contribution of edge (s,d) in relation r to Bcat[d, b*64+i] is C[r,b]*invdeg_r[d]*h[s][i].
__global__ void k_scatter(const float* __restrict__ h, const int* __restrict__ edges,
                          const float* __restrict__ Cmat, int useflag) {
    int gid = blockIdx.x * blockDim.x + threadIdx.x;
    int warp = gid >> 5;
    if (warp >= RR * EE) return;
    int lane = gid & 31;
    int r = warp / EE;
    int2 ed = reinterpret_cast<const int2*>(edges)[warp];   // (src, dst)
    if (useflag && !g_isseed[ed.y]) return;
    int b = lane >> 4, c = lane & 15;
    float w = __ldg(&Cmat[r * 2 + b]) * g_deg[r * NN + ed.y];
    float4 xv = *reinterpret_cast<const float4*>(&h[(size_t)ed.x * 64 + c * 4]);
    red_add4(&g_Bcat[(size_t)ed.y * 128 + b * 64 + c * 4],
             xv.x * w, xv.y * w, xv.z * w, xv.w * w);
}

__global__ void k_zeroseed(const int* __restrict__ seeds) {
    int gid = blockIdx.x * blockDim.x + threadIdx.x;
    int s = gid >> 5;
    if (s >= SS) return;
    int lane = gid & 31;
    int node = seeds[s];
    reinterpret_cast<float4*>(&g_Bcat[(size_t)node * 128])[lane] = make_float4(0.f, 0.f, 0.f, 0.f);
}

__global__ void k_gatherseed(const int* __restrict__ seeds) {
    int gid = blockIdx.x * blockDim.x + threadIdx.x;
    int s = gid >> 5;
    if (s >= SS) return;
    int lane = gid & 31;
    int node = seeds[s];
    reinterpret_cast<float4*>(&g_sA[(size_t)s * 128])[lane] =
        reinterpret_cast<const float4*>(&g_Bcat[(size_t)node * 128])[lane];
}

__global__ void k_addnoise(const float* __restrict__ noise, const int* __restrict__ seeds) {
    int i = blockIdx.x * blockDim.x + threadIdx.x;
    if (i >= SS * 64) return;
    int s = i >> 6;
    g_hs[i] += noise[(size_t)seeds[s] * 64 + (i & 63)];
}

__global__ void k_d3(const float* __restrict__ Wd3, const float* __restrict__ bd3,
                     float* __restrict__ out) {
    int i = blockIdx.x * blockDim.x + threadIdx.x;
    if (i >= PP * SS) return;
    int p = i / SS;
    const float* v = &g_D2[(size_t)i * 32];
    const float* w = &Wd3[p * 32];
    float sum = bd3[p];
#pragma unroll
    for (int k = 0; k < 32; k++) sum += v[k] * w[k];
    out[i] = fmaxf(sum, 0.0f);
}

// ------------------------- generic fused GEMM: C = act(A@W + bias) -------------------------
// A: [M,K] row-major (ld=K), W: [K,N] row-major (ld=N), C: [M,N] row-major.
// Batched over blockIdx.z with element strides strA/strW/strBias/strC.
// act: 0=none, 1=relu, 2=leaky(0.01), 3=tanh. Requires K % 8 == 0, K % 4 == 0 for float4 A loads.
template <int BN, int TN>
__global__ __launch_bounds__(256)
void gemm_kernel(const float* __restrict__ A, size_t strA,
                 const float* __restrict__ W, size_t strW,
                 const float* __restrict__ bias, size_t strBias, int hasBias,
                 float* __restrict__ C, size_t strC,
                 int M, int N, int K, int act) {
    constexpr int BM = 128, BK = 8;
    constexpr int TX = BN / TN;          // 16
    constexpr int BLD = BK * BN / 256;   // 4 (BN=128) or 2 (BN=64)
    __shared__ float As[BK][BM + 4];
    __shared__ float Bs[BK][BN];

    int tid = threadIdx.x;
    int p = blockIdx.z;
    A += (size_t)p * strA;
    W += (size_t)p * strW;
    C += (size_t)p * strC;
    const float* bp = hasBias ? (bias + (size_t)p * strBias) : nullptr;

    int row0 = blockIdx.y * BM, col0 = blockIdx.x * BN;
    int tx = tid % TX, ty = tid / TX;    // ty in [0,16): rows ty*8..+7 ; cols tx*TN..+TN-1

    float acc[8][TN];
#pragma unroll
    for (int i = 0; i < 8; i++)
#pragma unroll
        for (int j = 0; j < TN; j++) acc[i][j] = 0.f;

    int arow = tid >> 1, acol = (tid & 1) * 4;

    for (int kt = 0; kt < K; kt += BK) {
        // global loads into registers
        float4 av = make_float4(0.f, 0.f, 0.f, 0.f);
        int gr = row0 + arow;
        if (gr < M) av = *reinterpret_cast<const float4*>(&A[(size_t)gr * K + kt + acol]);
        float bv[BLD];
#pragma unroll
        for (int i = 0; i < BLD; i++) {
            int lin = tid * BLD + i;
            int gc = col0 + (lin % BN);
            bv[i] = (gc < N) ? W[(size_t)(kt + lin / BN) * N + gc] : 0.f;
        }
        __syncthreads();
        As[acol + 0][arow] = av.x;
        As[acol + 1][arow] = av.y;
        As[acol + 2][arow] = av.z;
        As[acol + 3][arow] = av.w;
#pragma unroll
        for (int i = 0; i < BLD; i++) {
            int lin = tid * BLD + i;
            Bs[lin / BN][lin % BN] = bv[i];
        }
        __syncthreads();
#pragma unroll
        for (int k = 0; k < BK; k++) {
            float a[8], b[TN];
            *reinterpret_cast<float4*>(&a[0]) = *reinterpret_cast<const float4*>(&As[k][ty * 8]);
            *reinterpret_cast<float4*>(&a[4]) = *reinterpret_cast<const float4*>(&As[k][ty * 8 + 4]);
#pragma unroll
            for (int j = 0; j < TN; j += 4)
                *reinterpret_cast<float4*>(&b[j]) = *reinterpret_cast<const float4*>(&Bs[k][tx * TN + j]);
#pragma unroll
            for (int i = 0; i < 8; i++)
#pragma unroll
                for (int j = 0; j < TN; j++) acc[i][j] += a[i] * b[j];
        }
    }

    // epilogue
#pragma unroll
    for (int i = 0; i < 8; i++) {
        int gr = row0 + ty * 8 + i;
        if (gr >= M) continue;
#pragma unroll
        for (int j = 0; j < TN; j++) {
            int gc = col0 + tx * TN + j;
            if (gc >= N) continue;
            float v = acc[i][j] + (bp ? bp[gc] : 0.f);
            if (act == 1)      v = fmaxf(v, 0.f);
            else if (act == 2) v = (v > 0.f) ? v : 0.01f * v;
            else if (act == 3) v = tanhf(v);
            C[(size_t)gr * N + gc] = v;
        }
    }
}

// ------------------------- launcher -------------------------
extern "C" void kernel_launch(void* const* d_in, const int* in_sizes, int n_in,
                              void* d_out, int out_size) {
    (void)in_sizes; (void)n_in; (void)out_size;
    const float* x     = (const float*)d_in[0];
    const int*   edges = (const int*)d_in[1];
    const int*   seeds = (const int*)d_in[2];
    const float* noise = (const float*)d_in[3];
    const float* V1    = (const float*)d_in[4];
    const float* C1    = (const float*)d_in[5];
    const float* V2    = (const float*)d_in[6];
    const float* C2    = (const float*)d_in[7];
    const float* W_lin = (const float*)d_in[8];
    const float* b_lin = (const float*)d_in[9];
    const float* Wd1   = (const float*)d_in[10];
    const float* bd1   = (const float*)d_in[11];
    const float* Wd2   = (const float*)d_in[12];
    const float* bd2   = (const float*)d_in[13];
    const float* Wd3   = (const float*)d_in[14];
    const float* bd3   = (const float*)d_in[15];
    const float* Wf1   = (const float*)d_in[16];
    const float* bf1   = (const float*)d_in[17];
    const float* Wf2   = (const float*)d_in[18];
    const float* bf2   = (const float*)d_in[19];
    const float* Wf3   = (const float*)d_in[20];
    const float* bf3   = (const float*)d_in[21];
    float* out = (float*)d_out;

    void *pDeg, *pBcat, *pIs, *pH1, *pSA, *pH2, *pHs, *pD1, *pD2, *pF1, *pF2;
    cudaGetSymbolAddress(&pDeg, g_deg);
    cudaGetSymbolAddress(&pBcat, g_Bcat);
    cudaGetSymbolAddress(&pIs, g_isseed);
    cudaGetSymbolAddress(&pH1, g_h1);
    cudaGetSymbolAddress(&pSA, g_sA);
    cudaGetSymbolAddress(&pH2, g_h2);
    cudaGetSymbolAddress(&pHs, g_hs);
    cudaGetSymbolAddress(&pD1, g_D1);
    cudaGetSymbolAddress(&pD2, g_D2);
    cudaGetSymbolAddress(&pF1, g_F1);
    cudaGetSymbolAddress(&pF2, g_F2);
    float* dBcat = (float*)pBcat;
    float* dH1   = (float*)pH1;
    float* dSA   = (float*)pSA;
    float* dH2   = (float*)pH2;
    float* dHs   = (float*)pHs;
    float* dD1   = (float*)pD1;
    float* dD2   = (float*)pD2;
    float* dF1   = (float*)pF1;
    float* dF2   = (float*)pF2;
    (void)dD2;

    // zero accumulators + flags
    cudaMemsetAsync(pDeg, 0, sizeof(float) * RR * NN);
    cudaMemsetAsync(pBcat, 0, sizeof(float) * (size_t)NN * 128);
    cudaMemsetAsync(pIs, 0, NN);

    const int scatterBlocks = (RR * EE * 32 + 255) / 256;

    k_seedflag<<<(SS + 255) / 256, 256>>>(seeds);
    k_deg<<<(RR * EE + 255) / 256, 256>>>(edges);
    k_invdeg<<<(RR * NN + 255) / 256, 256>>>();

    // ---- conv layer 1 (full graph) ----
    k_scatter<<<scatterBlocks, 256>>>(x, edges, C1, 0);
    gemm_kernel<64, 4><<<dim3(1, (NN + 127) / 128, 1), 256>>>(
        dBcat, 0, V1, 0, nullptr, 0, 0, dH1, 0, NN, 64, 128, 1);

    // ---- conv layer 2 (seed destinations only) ----
    k_zeroseed<<<(SS * 32 + 255) / 256, 256>>>(seeds);
    k_scatter<<<scatterBlocks, 256>>>(dH1, edges, C2, 1);
    k_gatherseed<<<(SS * 32 + 255) / 256, 256>>>(seeds);
    gemm_kernel<64, 4><<<dim3(1, SS / 128, 1), 256>>>(
        dSA, 0, V2, 0, nullptr, 0, 0, dH2, 0, SS, 64, 128, 1);

    // ---- linear + leaky + noise at seeds ----
    gemm_kernel<64, 4><<<dim3(1, SS / 128, 1), 256>>>(
        dH2, 0, W_lin, 0, b_lin, 0, 1, dHs, 0, SS, 64, 64, 2);
    k_addnoise<<<(SS * 64 + 255) / 256, 256>>>(noise, seeds);

    // ---- d branch ----
    gemm_kernel<128, 8><<<dim3(2, SS / 128, PP), 256>>>(
        dHs, 0, Wd1, (size_t)64 * 256, bd1, 256, 1, dD1, (size_t)SS * 256, SS, 256, 64, 2);
    gemm_kernel<64, 4><<<dim3(1, SS / 128, PP), 256>>>(
        dD1, (size_t)SS * 256, Wd2, (size_t)256 * 32, bd2, 32, 1, dD2, (size_t)SS * 32, SS, 32, 256, 2);
    k_d3<<<(PP * SS + 255) / 256, 256>>>(Wd3, bd3, out);

    // ---- f branch ----
    gemm_kernel<128, 8><<<dim3(2, SS / 128, PP), 256>>>(
        dHs, 0, Wf1, (size_t)64 * 256, bf1, 256, 1, dF1, (size_t)SS * 256, SS, 256, 64, 1);
    gemm_kernel<128, 8><<<dim3(16, SS / 128, PP), 256>>>(
        dF1, (size_t)SS * 256, Wf2, (size_t)256 * 2048, bf2, 2048, 1, dF2, (size_t)SS * 2048, SS, 2048, 256, 1);
    gemm_kernel<128, 8><<<dim3(3, SS / 128, PP), 256>>>(
        dF2, (size_t)SS * 2048, Wf3, (size_t)2048 * 320, bf3, 320, 1, out + PP * SS, (size_t)SS * 320, SS, 320, 2048, 3);
}

// round 4
// speedup vs baseline: 1.7906x; 1.7906x over previous
#include <cuda_runtime.h>
#include <cstdint>
#include <cstddef>

#define NN 100000
#define RR 4
#define EE 300000
#define HH 64
#define SS 4096
#define PP 2

// ------------------------- scratch (static device globals; no allocs) -------------------------
__device__ float g_deg[RR * NN];                 // degree, then in-place inverse degree
__device__ float g_Bcat[(size_t)NN * 128];       // aggregated [B0 | B1] per node
__device__ float g_h1[(size_t)NN * HH];          // layer-1 output
__device__ unsigned char g_isseed[NN];
__device__ float g_sA[SS * 128];                 // Bcat gathered at seeds
__device__ float g_h2[SS * HH];
__device__ float g_hs[SS * HH];
__device__ float g_D1[PP * SS * 256];
__device__ float g_D2[PP * SS * 32];
__device__ float g_F1[PP * SS * 256];
__device__ float g_F2[(size_t)PP * SS * 2048];

// ------------------------- helpers -------------------------
__device__ __forceinline__ void red_add4(float* p, float a, float b, float c, float d) {
    asm volatile("red.global.add.v4.f32 [%0], {%1,%2,%3,%4};" ::
                 "l"(p), "f"(a), "f"(b), "f"(c), "f"(d) : "memory");
}

__device__ __forceinline__ uint32_t f2tf(float x) {
    uint32_t u;
    asm("cvt.rna.tf32.f32 %0, %1;" : "=r"(u) : "f"(x));
    return u;
}

__device__ __forceinline__ void mma_tf32(float* c, const uint32_t* a, const uint32_t* b) {
    asm volatile(
        "mma.sync.aligned.m16n8k8.row.col.f32.tf32.tf32.f32 "
        "{%0,%1,%2,%3},{%4,%5,%6,%7},{%8,%9},{%0,%1,%2,%3};"
        : "+f"(c[0]), "+f"(c[1]), "+f"(c[2]), "+f"(c[3])
        : "r"(a[0]), "r"(a[1]), "r"(a[2]), "r"(a[3]), "r"(b[0]), "r"(b[1]));
}

// ------------------------- small kernels -------------------------
__global__ void k_seedflag(const int* __restrict__ seeds) {
    int i = blockIdx.x * blockDim.x + threadIdx.x;
    if (i < SS) g_isseed[seeds[i]] = 1;
}

__global__ void k_deg(const int* __restrict__ edges) {
    int i = blockIdx.x * blockDim.x + threadIdx.x;
    if (i >= RR * EE) return;
    int r = i / EE;
    int dst = edges[2 * i + 1];
    atomicAdd(&g_deg[r * NN + dst], 1.0f);
}

__global__ void k_invdeg() {
    int i = blockIdx.x * blockDim.x + threadIdx.x;
    if (i < RR * NN) g_deg[i] = 1.0f / fmaxf(g_deg[i], 1.0f);
}

// One warp per edge. lanes 0-15 accumulate basis b=0, lanes 16-31 basis b=1.
__global__ void k_scatter(const float* __restrict__ h, const int* __restrict__ edges,
                          const float* __restrict__ Cmat, int useflag) {
    int gid = blockIdx.x * blockDim.x + threadIdx.x;
    int warp = gid >> 5;
    if (warp >= RR * EE) return;
    int lane = gid & 31;
    int r = warp / EE;
    int2 ed = reinterpret_cast<const int2*>(edges)[warp];   // (src, dst)
    if (useflag && !g_isseed[ed.y]) return;
    int b = lane >> 4, c = lane & 15;
    float w = __ldg(&Cmat[r * 2 + b]) * g_deg[r * NN + ed.y];
    float4 xv = *reinterpret_cast<const float4*>(&h[(size_t)ed.x * 64 + c * 4]);
    red_add4(&g_Bcat[(size_t)ed.y * 128 + b * 64 + c * 4],
             xv.x * w, xv.y * w, xv.z * w, xv.w * w);
}

__global__ void k_zeroseed(const int* __restrict__ seeds) {
    int gid = blockIdx.x * blockDim.x + threadIdx.x;
    int s = gid >> 5;
    if (s >= SS) return;
    int lane = gid & 31;
    int node = seeds[s];
    reinterpret_cast<float4*>(&g_Bcat[(size_t)node * 128])[lane] = make_float4(0.f, 0.f, 0.f, 0.f);
}

__global__ void k_gatherseed(const int* __restrict__ seeds) {
    int gid = blockIdx.x * blockDim.x + threadIdx.x;
    int s = gid >> 5;
    if (s >= SS) return;
    int lane = gid & 31;
    int node = seeds[s];
    reinterpret_cast<float4*>(&g_sA[(size_t)s * 128])[lane] =
        reinterpret_cast<const float4*>(&g_Bcat[(size_t)node * 128])[lane];
}

__global__ void k_addnoise(const float* __restrict__ noise, const int* __restrict__ seeds) {
    int i = blockIdx.x * blockDim.x + threadIdx.x;
    if (i >= SS * 64) return;
    int s = i >> 6;
    g_hs[i] += noise[(size_t)seeds[s] * 64 + (i & 63)];
}

__global__ void k_d3(const float* __restrict__ Wd3, const float* __restrict__ bd3,
                     float* __restrict__ out) {
    int i = blockIdx.x * blockDim.x + threadIdx.x;
    if (i >= PP * SS) return;
    int p = i / SS;
    const float* v = &g_D2[(size_t)i * 32];
    const float* w = &Wd3[p * 32];
    float sum = bd3[p];
#pragma unroll
    for (int k = 0; k < 32; k++) sum += v[k] * w[k];
    out[i] = fmaxf(sum, 0.0f);
}

// ------------------------- tf32 tensor-core GEMM: C = act(A@W + bias) -------------------------
// A: [M,K] row-major. W: [K,N] row-major. C: [M,N] row-major. Batched over blockIdx.z.
// Requires K % 16 == 0, N % 4 == 0. act: 0=none, 1=relu, 2=leaky(0.01), 3=tanh.
// BM=128, BK=16, 8 warps. Warp tile WM x WN via m16n8k8 tf32 mma.
template <int BN, int WM, int WN>
__global__ __launch_bounds__(256, 1)
void mma_gemm(const float* __restrict__ A, size_t strA,
              const float* __restrict__ W, size_t strW,
              const float* __restrict__ bias, size_t strBias, int hasBias,
              float* __restrict__ C, size_t strC,
              int M, int N, int K, int act) {
    constexpr int BM = 128, BK = 16;
    constexpr int MT = WM / 16, NT = WN / 8;
    constexpr int SKA = BK + 4;           // 20: conflict-free A-fragment loads
    constexpr int SKB = BN + 8;           // 8*t4+g hits 32 distinct banks
    constexpr int A4 = BM * BK / 4 / 256; // float4 A loads per thread (2)
    constexpr int B4 = BK * BN / 4 / 256; // float4 B loads per thread (2 or 1)
    constexpr int WARPS_M = BM / WM;

    __shared__ uint32_t As[2][BM * SKA];
    __shared__ uint32_t Bs[2][BK * SKB];

    int tid = threadIdx.x, lane = tid & 31, wid = tid >> 5;
    int g = lane >> 2, t4 = lane & 3;
    int wm = (wid % WARPS_M) * WM;
    int wn = (wid / WARPS_M) * WN;

    int p = blockIdx.z;
    A += (size_t)p * strA;
    W += (size_t)p * strW;
    C += (size_t)p * strC;
    const float* bp = hasBias ? (bias + (size_t)p * strBias) : nullptr;

    int row0 = blockIdx.y * BM, col0 = blockIdx.x * BN;

    float acc[MT][NT][4];
#pragma unroll
    for (int mt = 0; mt < MT; mt++)
#pragma unroll
        for (int nt = 0; nt < NT; nt++)
#pragma unroll
            for (int i = 0; i < 4; i++) acc[mt][nt][i] = 0.f;

    float4 va[A4], vb[B4 > 0 ? B4 : 1];

    auto ldg_tile = [&](int kt) {
#pragma unroll
        for (int i = 0; i < A4; i++) {
            int idx = tid + i * 256;
            int r = idx >> 2;                 // BK/4 = 4 float4 per A row
            int c4 = (idx & 3) * 4;
            int gr = row0 + r;
            va[i] = (gr < M) ? *reinterpret_cast<const float4*>(&A[(size_t)gr * K + kt + c4])
                             : make_float4(0.f, 0.f, 0.f, 0.f);
        }
#pragma unroll
        for (int i = 0; i < B4; i++) {
            int idx = tid + i * 256;
            int r = idx / (BN / 4);
            int c4 = (idx % (BN / 4)) * 4;
            int gc = col0 + c4;
            vb[i] = (gc < N) ? *reinterpret_cast<const float4*>(&W[(size_t)(kt + r) * N + gc])
                             : make_float4(0.f, 0.f, 0.f, 0.f);
        }
    };
    auto sts_tile = [&](int buf) {
#pragma unroll
        for (int i = 0; i < A4; i++) {
            int idx = tid + i * 256;
            int r = idx >> 2;
            int c4 = (idx & 3) * 4;
            uint4 u = make_uint4(f2tf(va[i].x), f2tf(va[i].y), f2tf(va[i].z), f2tf(va[i].w));
            *reinterpret_cast<uint4*>(&As[buf][r * SKA + c4]) = u;
        }
#pragma unroll
        for (int i = 0; i < B4; i++) {
            int idx = tid + i * 256;
            int r = idx / (BN / 4);
            int c4 = (idx % (BN / 4)) * 4;
            uint4 u = make_uint4(f2tf(vb[i].x), f2tf(vb[i].y), f2tf(vb[i].z), f2tf(vb[i].w));
            *reinterpret_cast<uint4*>(&Bs[buf][r * SKB + c4]) = u;
        }
    };

    int ntiles = K / BK;
    ldg_tile(0);
    sts_tile(0);
    __syncthreads();
    int cur = 0;

    for (int kt = 0; kt < ntiles; kt++) {
        if (kt + 1 < ntiles) ldg_tile((kt + 1) * BK);
#pragma unroll
        for (int ks = 0; ks < BK; ks += 8) {
            uint32_t af[MT][4], bf[NT][2];
#pragma unroll
            for (int mt = 0; mt < MT; mt++) {
                const uint32_t* base = &As[cur][(wm + mt * 16) * SKA + ks + t4];
                af[mt][0] = base[g * SKA];
                af[mt][1] = base[(g + 8) * SKA];
                af[mt][2] = base[g * SKA + 4];
                af[mt][3] = base[(g + 8) * SKA + 4];
            }
#pragma unroll
            for (int nt = 0; nt < NT; nt++) {
                const uint32_t* base = &Bs[cur][(ks + t4) * SKB + wn + nt * 8 + g];
                bf[nt][0] = base[0];
                bf[nt][1] = base[4 * SKB];
            }
#pragma unroll
            for (int mt = 0; mt < MT; mt++)
#pragma unroll
                for (int nt = 0; nt < NT; nt++)
                    mma_tf32(acc[mt][nt], af[mt], bf[nt]);
        }
        if (kt + 1 < ntiles) {
            sts_tile(cur ^ 1);
            __syncthreads();
            cur ^= 1;
        }
    }

    // epilogue
#pragma unroll
    for (int mt = 0; mt < MT; mt++) {
#pragma unroll
        for (int nt = 0; nt < NT; nt++) {
            int gc = col0 + wn + nt * 8 + t4 * 2;
            if (gc >= N) continue;
            float bias0 = bp ? bp[gc] : 0.f;
            float bias1 = bp ? bp[gc + 1] : 0.f;
#pragma unroll
            for (int h = 0; h < 2; h++) {
                int gr = row0 + wm + mt * 16 + g + h * 8;
                if (gr >= M) continue;
                float v0 = acc[mt][nt][2 * h + 0] + bias0;
                float v1 = acc[mt][nt][2 * h + 1] + bias1;
                if (act == 1)      { v0 = fmaxf(v0, 0.f); v1 = fmaxf(v1, 0.f); }
                else if (act == 2) { v0 = (v0 > 0.f) ? v0 : 0.01f * v0;
                                     v1 = (v1 > 0.f) ? v1 : 0.01f * v1; }
                else if (act == 3) { v0 = tanhf(v0); v1 = tanhf(v1); }
                *reinterpret_cast<float2*>(&C[(size_t)gr * N + gc]) = make_float2(v0, v1);
            }
        }
    }
}

// ------------------------- launcher -------------------------
extern "C" void kernel_launch(void* const* d_in, const int* in_sizes, int n_in,
                              void* d_out, int out_size) {
    (void)in_sizes; (void)n_in; (void)out_size;
    const float* x     = (const float*)d_in[0];
    const int*   edges = (const int*)d_in[1];
    const int*   seeds = (const int*)d_in[2];
    const float* noise = (const float*)d_in[3];
    const float* V1    = (const float*)d_in[4];
    const float* C1    = (const float*)d_in[5];
    const float* V2    = (const float*)d_in[6];
    const float* C2    = (const float*)d_in[7];
    const float* W_lin = (const float*)d_in[8];
    const float* b_lin = (const float*)d_in[9];
    const float* Wd1   = (const float*)d_in[10];
    const float* bd1   = (const float*)d_in[11];
    const float* Wd2   = (const float*)d_in[12];
    const float* bd2   = (const float*)d_in[13];
    const float* Wd3   = (const float*)d_in[14];
    const float* bd3   = (const float*)d_in[15];
    const float* Wf1   = (const float*)d_in[16];
    const float* bf1   = (const float*)d_in[17];
    const float* Wf2   = (const float*)d_in[18];
    const float* bf2   = (const float*)d_in[19];
    const float* Wf3   = (const float*)d_in[20];
    const float* bf3   = (const float*)d_in[21];
    float* out = (float*)d_out;

    void *pDeg, *pBcat, *pIs, *pH1, *pSA, *pH2, *pHs, *pD1, *pD2, *pF1, *pF2;
    cudaGetSymbolAddress(&pDeg, g_deg);
    cudaGetSymbolAddress(&pBcat, g_Bcat);
    cudaGetSymbolAddress(&pIs, g_isseed);
    cudaGetSymbolAddress(&pH1, g_h1);
    cudaGetSymbolAddress(&pSA, g_sA);
    cudaGetSymbolAddress(&pH2, g_h2);
    cudaGetSymbolAddress(&pHs, g_hs);
    cudaGetSymbolAddress(&pD1, g_D1);
    cudaGetSymbolAddress(&pD2, g_D2);
    cudaGetSymbolAddress(&pF1, g_F1);
    cudaGetSymbolAddress(&pF2, g_F2);
    float* dBcat = (float*)pBcat;
    float* dH1   = (float*)pH1;
    float* dSA   = (float*)pSA;
    float* dH2   = (float*)pH2;
    float* dHs   = (float*)pHs;
    float* dD1   = (float*)pD1;
    float* dD2   = (float*)pD2;
    float* dF1   = (float*)pF1;
    float* dF2   = (float*)pF2;

    // zero accumulators + flags
    cudaMemsetAsync(pDeg, 0, sizeof(float) * RR * NN);
    cudaMemsetAsync(pBcat, 0, sizeof(float) * (size_t)NN * 128);
    cudaMemsetAsync(pIs, 0, NN);

    const int scatterBlocks = (RR * EE * 32 + 255) / 256;

    k_seedflag<<<(SS + 255) / 256, 256>>>(seeds);
    k_deg<<<(RR * EE + 255) / 256, 256>>>(edges);
    k_invdeg<<<(RR * NN + 255) / 256, 256>>>();

    // ---- conv layer 1 (full graph) ----
    k_scatter<<<scatterBlocks, 256>>>(x, edges, C1, 0);
    mma_gemm<64, 32, 32><<<dim3(1, (NN + 127) / 128, 1), 256>>>(
        dBcat, 0, V1, 0, nullptr, 0, 0, dH1, 0, NN, 64, 128, 1);

    // ---- conv layer 2 (seed destinations only) ----
    k_zeroseed<<<(SS * 32 + 255) / 256, 256>>>(seeds);
    k_scatter<<<scatterBlocks, 256>>>(dH1, edges, C2, 1);
    k_gatherseed<<<(SS * 32 + 255) / 256, 256>>>(seeds);
    mma_gemm<64, 32, 32><<<dim3(1, SS / 128, 1), 256>>>(
        dSA, 0, V2, 0, nullptr, 0, 0, dH2, 0, SS, 64, 128, 1);

    // ---- linear + leaky + noise at seeds ----
    mma_gemm<64, 32, 32><<<dim3(1, SS / 128, 1), 256>>>(
        dH2, 0, W_lin, 0, b_lin, 0, 1, dHs, 0, SS, 64, 64, 2);
    k_addnoise<<<(SS * 64 + 255) / 256, 256>>>(noise, seeds);

    // ---- d branch ----
    mma_gemm<128, 64, 32><<<dim3(2, SS / 128, PP), 256>>>(
        dHs, 0, Wd1, (size_t)64 * 256, bd1, 256, 1, dD1, (size_t)SS * 256, SS, 256, 64, 2);
    mma_gemm<64, 32, 32><<<dim3(1, SS / 128, PP), 256>>>(
        dD1, (size_t)SS * 256, Wd2, (size_t)256 * 32, bd2, 32, 1, dD2, (size_t)SS * 32, SS, 32, 256, 2);
    k_d3<<<(PP * SS + 255) / 256, 256>>>(Wd3, bd3, out);

    // ---- f branch ----
    mma_gemm<128, 64, 32><<<dim3(2, SS / 128, PP), 256>>>(
        dHs, 0, Wf1, (size_t)64 * 256, bf1, 256, 1, dF1, (size_t)SS * 256, SS, 256, 64, 1);
    mma_gemm<128, 64, 32><<<dim3(16, SS / 128, PP), 256>>>(
        dF1, (size_t)SS * 256, Wf2, (size_t)256 * 2048, bf2, 2048, 1, dF2, (size_t)SS * 2048, SS, 2048, 256, 1);
    mma_gemm<128, 64, 32><<<dim3(3, SS / 128, PP), 256>>>(
        dF2, (size_t)SS * 2048, Wf3, (size_t)2048 * 320, bf3, 320, 1, out + PP * SS, (size_t)SS * 320, SS, 320, 2048, 3);
}

// round 5
// speedup vs baseline: 2.4997x; 1.3960x over previous
#include <cuda_runtime.h>
#include <cstdint>
#include <cstddef>

#define NN 100000
#define RR 4
#define EE 300000
#define HH 64
#define SS 4096
#define PP 2

// ------------------------- scratch (static device globals; no allocs) -------------------------
__device__ float g_deg[RR * NN];                 // degree, then in-place inverse degree
__device__ float g_A[(size_t)RR * NN * 64];      // per-relation unweighted aggregation
__device__ float g_Bcat[(size_t)NN * 128];       // combined [B0 | B1] per node
__device__ float g_h1[(size_t)NN * HH];          // layer-1 output
__device__ unsigned char g_isseed[NN];
__device__ float g_sA[SS * 128];                 // combined layer-2 features at seeds
__device__ float g_h2[SS * HH];
__device__ float g_hs[SS * HH];
__device__ float g_D1[PP * SS * 256];
__device__ float g_D2[PP * SS * 32];
__device__ float g_F1[PP * SS * 256];
__device__ float g_F2[(size_t)PP * SS * 2048];

// ------------------------- helpers -------------------------
__device__ __forceinline__ void red_add4(float* p, float a, float b, float c, float d) {
    asm volatile("red.global.add.v4.f32 [%0], {%1,%2,%3,%4};" ::
                 "l"(p), "f"(a), "f"(b), "f"(c), "f"(d) : "memory");
}

__device__ __forceinline__ uint32_t f2tf(float x) {
    uint32_t u;
    asm("cvt.rna.tf32.f32 %0, %1;" : "=r"(u) : "f"(x));
    return u;
}

__device__ __forceinline__ void mma_tf32(float* c, const uint32_t* a, const uint32_t* b) {
    asm volatile(
        "mma.sync.aligned.m16n8k8.row.col.f32.tf32.tf32.f32 "
        "{%0,%1,%2,%3},{%4,%5,%6,%7},{%8,%9},{%0,%1,%2,%3};"
        : "+f"(c[0]), "+f"(c[1]), "+f"(c[2]), "+f"(c[3])
        : "r"(a[0]), "r"(a[1]), "r"(a[2]), "r"(a[3]), "r"(b[0]), "r"(b[1]));
}

// ------------------------- small kernels -------------------------
__global__ void k_seedflag(const int* __restrict__ seeds) {
    int i = blockIdx.x * blockDim.x + threadIdx.x;
    if (i < SS) g_isseed[seeds[i]] = 1;
}

__global__ void k_deg(const int* __restrict__ edges) {
    int i = blockIdx.x * blockDim.x + threadIdx.x;
    if (i >= RR * EE) return;
    int r = i / EE;
    int dst = edges[2 * i + 1];
    atomicAdd(&g_deg[r * NN + dst], 1.0f);
}

__global__ void k_invdeg() {
    int i = blockIdx.x * blockDim.x + threadIdx.x;
    if (i < RR * NN) g_deg[i] = 1.0f / fmaxf(g_deg[i], 1.0f);
}

// Pure structural scatter: A[r][dst] += h[src]. 16 lanes per edge (2 edges/warp).
__global__ void k_scatterA(const float* __restrict__ h, const int* __restrict__ edges,
                           int useflag) {
    int gid = blockIdx.x * blockDim.x + threadIdx.x;
    int e = gid >> 4;
    if (e >= RR * EE) return;
    int l = gid & 15;
    int r = e / EE;
    int2 ed = reinterpret_cast<const int2*>(edges)[e];   // (src, dst)
    if (useflag && !g_isseed[ed.y]) return;
    float4 xv = *reinterpret_cast<const float4*>(&h[(size_t)ed.x * 64 + l * 4]);
    red_add4(&g_A[((size_t)r * NN + ed.y) * 64 + l * 4], xv.x, xv.y, xv.z, xv.w);
}

// Bcat[n, b*64+i] = sum_r C[r,b] * invdeg_r[n] * A[r][n][i]   (16 threads per node)
__global__ void k_combine1(const float* __restrict__ Cmat) {
    int idx = blockIdx.x * blockDim.x + threadIdx.x;
    if (idx >= NN * 16) return;
    int n = idx >> 4, i4 = idx & 15;
    float4 o0 = make_float4(0.f, 0.f, 0.f, 0.f);
    float4 o1 = make_float4(0.f, 0.f, 0.f, 0.f);
#pragma unroll
    for (int r = 0; r < RR; r++) {
        float inv = __ldg(&g_deg[r * NN + n]);
        float c0 = __ldg(&Cmat[r * 2 + 0]) * inv;
        float c1 = __ldg(&Cmat[r * 2 + 1]) * inv;
        float4 a = *reinterpret_cast<const float4*>(&g_A[((size_t)r * NN + n) * 64 + i4 * 4]);
        o0.x += c0 * a.x; o0.y += c0 * a.y; o0.z += c0 * a.z; o0.w += c0 * a.w;
        o1.x += c1 * a.x; o1.y += c1 * a.y; o1.z += c1 * a.z; o1.w += c1 * a.w;
    }
    *reinterpret_cast<float4*>(&g_Bcat[(size_t)n * 128 + i4 * 4]) = o0;
    *reinterpret_cast<float4*>(&g_Bcat[(size_t)n * 128 + 64 + i4 * 4]) = o1;
}

// zero A rows for seed nodes only (thread per (s, r, i4))
__global__ void k_zeroAseed(const int* __restrict__ seeds) {
    int idx = blockIdx.x * blockDim.x + threadIdx.x;
    if (idx >= SS * RR * 16) return;
    int s = idx >> 6;
    int r = (idx >> 4) & 3;
    int i4 = idx & 15;
    int node = seeds[s];
    *reinterpret_cast<float4*>(&g_A[((size_t)r * NN + node) * 64 + i4 * 4]) =
        make_float4(0.f, 0.f, 0.f, 0.f);
}

// sA[s, b*64+i] = sum_r C2[r,b] * invdeg_r[node] * A[r][node][i]  (16 threads per seed)
__global__ void k_combine2(const float* __restrict__ Cmat, const int* __restrict__ seeds) {
    int idx = blockIdx.x * blockDim.x + threadIdx.x;
    if (idx >= SS * 16) return;
    int s = idx >> 4, i4 = idx & 15;
    int n = seeds[s];
    float4 o0 = make_float4(0.f, 0.f, 0.f, 0.f);
    float4 o1 = make_float4(0.f, 0.f, 0.f, 0.f);
#pragma unroll
    for (int r = 0; r < RR; r++) {
        float inv = __ldg(&g_deg[r * NN + n]);
        float c0 = __ldg(&Cmat[r * 2 + 0]) * inv;
        float c1 = __ldg(&Cmat[r * 2 + 1]) * inv;
        float4 a = *reinterpret_cast<const float4*>(&g_A[((size_t)r * NN + n) * 64 + i4 * 4]);
        o0.x += c0 * a.x; o0.y += c0 * a.y; o0.z += c0 * a.z; o0.w += c0 * a.w;
        o1.x += c1 * a.x; o1.y += c1 * a.y; o1.z += c1 * a.z; o1.w += c1 * a.w;
    }
    *reinterpret_cast<float4*>(&g_sA[(size_t)s * 128 + i4 * 4]) = o0;
    *reinterpret_cast<float4*>(&g_sA[(size_t)s * 128 + 64 + i4 * 4]) = o1;
}

__global__ void k_addnoise(const float* __restrict__ noise, const int* __restrict__ seeds) {
    int i = blockIdx.x * blockDim.x + threadIdx.x;
    if (i >= SS * 64) return;
    int s = i >> 6;
    g_hs[i] += noise[(size_t)seeds[s] * 64 + (i & 63)];
}

__global__ void k_d3(const float* __restrict__ Wd3, const float* __restrict__ bd3,
                     float* __restrict__ out) {
    int i = blockIdx.x * blockDim.x + threadIdx.x;
    if (i >= PP * SS) return;
    int p = i / SS;
    const float* v = &g_D2[(size_t)i * 32];
    const float* w = &Wd3[p * 32];
    float sum = bd3[p];
#pragma unroll
    for (int k = 0; k < 32; k++) sum += v[k] * w[k];
    out[i] = fmaxf(sum, 0.0f);
}

// ------------------------- tf32 tensor-core GEMM: C = act(A@W + bias) -------------------------
// A: [M,K] row-major. W: [K,N] row-major. C: [M,N] row-major. Batched over blockIdx.z.
// Requires K % 16 == 0, N % 4 == 0. act: 0=none, 1=relu, 2=leaky(0.01), 3=tanh.
// BM=128, BK=16. Thread count = 32 * (BM/WM) * (BN/WN).
template <int BN, int WM, int WN>
__global__ __launch_bounds__(32 * (128 / WM) * (BN / WN), 1)
void mma_gemm(const float* __restrict__ A, size_t strA,
              const float* __restrict__ W, size_t strW,
              const float* __restrict__ bias, size_t strBias, int hasBias,
              float* __restrict__ C, size_t strC,
              int M, int N, int K, int act) {
    constexpr int BM = 128, BK = 16;
    constexpr int MT = WM / 16, NT = WN / 8;
    constexpr int WARPS_M = BM / WM;
    constexpr int NTH = 32 * WARPS_M * (BN / WN);
    constexpr int SKA = BK + 4;            // 20: conflict-free A-fragment loads
    constexpr int SKB = BN + 8;            // conflict-free B-fragment loads
    constexpr int A4 = BM * BK / 4 / NTH;  // float4 A loads per thread
    constexpr int B4 = BK * BN / 4 / NTH;  // float4 B loads per thread

    __shared__ uint32_t As[2][BM * SKA];
    __shared__ uint32_t Bs[2][BK * SKB];

    int tid = threadIdx.x, lane = tid & 31, wid = tid >> 5;
    int g = lane >> 2, t4 = lane & 3;
    int wm = (wid % WARPS_M) * WM;
    int wn = (wid / WARPS_M) * WN;

    int p = blockIdx.z;
    A += (size_t)p * strA;
    W += (size_t)p * strW;
    C += (size_t)p * strC;
    const float* bp = hasBias ? (bias + (size_t)p * strBias) : nullptr;

    int row0 = blockIdx.y * BM, col0 = blockIdx.x * BN;

    float acc[MT][NT][4];
#pragma unroll
    for (int mt = 0; mt < MT; mt++)
#pragma unroll
        for (int nt = 0; nt < NT; nt++)
#pragma unroll
            for (int i = 0; i < 4; i++) acc[mt][nt][i] = 0.f;

    float4 va[A4], vb[B4];

    auto ldg_tile = [&](int kt) {
#pragma unroll
        for (int i = 0; i < A4; i++) {
            int idx = tid + i * NTH;
            int r = idx >> 2;                 // BK/4 = 4 float4 per A row
            int c4 = (idx & 3) * 4;
            int gr = row0 + r;
            va[i] = (gr < M) ? *reinterpret_cast<const float4*>(&A[(size_t)gr * K + kt + c4])
                             : make_float4(0.f, 0.f, 0.f, 0.f);
        }
#pragma unroll
        for (int i = 0; i < B4; i++) {
            int idx = tid + i * NTH;
            int r = idx / (BN / 4);
            int c4 = (idx % (BN / 4)) * 4;
            int gc = col0 + c4;
            vb[i] = (gc < N) ? *reinterpret_cast<const float4*>(&W[(size_t)(kt + r) * N + gc])
                             : make_float4(0.f, 0.f, 0.f, 0.f);
        }
    };
    auto sts_tile = [&](int buf) {
#pragma unroll
        for (int i = 0; i < A4; i++) {
            int idx = tid + i * NTH;
            int r = idx >> 2;
            int c4 = (idx & 3) * 4;
            uint4 u = make_uint4(f2tf(va[i].x), f2tf(va[i].y), f2tf(va[i].z), f2tf(va[i].w));
            *reinterpret_cast<uint4*>(&As[buf][r * SKA + c4]) = u;
        }
#pragma unroll
        for (int i = 0; i < B4; i++) {
            int idx = tid + i * NTH;
            int r = idx / (BN / 4);
            int c4 = (idx % (BN / 4)) * 4;
            uint4 u = make_uint4(f2tf(vb[i].x), f2tf(vb[i].y), f2tf(vb[i].z), f2tf(vb[i].w));
            *reinterpret_cast<uint4*>(&Bs[buf][r * SKB + c4]) = u;
        }
    };

    int ntiles = K / BK;
    ldg_tile(0);
    sts_tile(0);
    __syncthreads();
    int cur = 0;

    for (int kt = 0; kt < ntiles; kt++) {
        if (kt + 1 < ntiles) ldg_tile((kt + 1) * BK);
#pragma unroll
        for (int ks = 0; ks < BK; ks += 8) {
            uint32_t af[MT][4], bf[NT][2];
#pragma unroll
            for (int mt = 0; mt < MT; mt++) {
                const uint32_t* base = &As[cur][(wm + mt * 16) * SKA + ks + t4];
                af[mt][0] = base[g * SKA];
                af[mt][1] = base[(g + 8) * SKA];
                af[mt][2] = base[g * SKA + 4];
                af[mt][3] = base[(g + 8) * SKA + 4];
            }
#pragma unroll
            for (int nt = 0; nt < NT; nt++) {
                const uint32_t* base = &Bs[cur][(ks + t4) * SKB + wn + nt * 8 + g];
                bf[nt][0] = base[0];
                bf[nt][1] = base[4 * SKB];
            }
#pragma unroll
            for (int mt = 0; mt < MT; mt++)
#pragma unroll
                for (int nt = 0; nt < NT; nt++)
                    mma_tf32(acc[mt][nt], af[mt], bf[nt]);
        }
        if (kt + 1 < ntiles) {
            sts_tile(cur ^ 1);
            __syncthreads();
            cur ^= 1;
        }
    }

    // epilogue
#pragma unroll
    for (int mt = 0; mt < MT; mt++) {
#pragma unroll
        for (int nt = 0; nt < NT; nt++) {
            int gc = col0 + wn + nt * 8 + t4 * 2;
            if (gc >= N) continue;
            float bias0 = bp ? bp[gc] : 0.f;
            float bias1 = bp ? bp[gc + 1] : 0.f;
#pragma unroll
            for (int h = 0; h < 2; h++) {
                int gr = row0 + wm + mt * 16 + g + h * 8;
                if (gr >= M) continue;
                float v0 = acc[mt][nt][2 * h + 0] + bias0;
                float v1 = acc[mt][nt][2 * h + 1] + bias1;
                if (act == 1)      { v0 = fmaxf(v0, 0.f); v1 = fmaxf(v1, 0.f); }
                else if (act == 2) { v0 = (v0 > 0.f) ? v0 : 0.01f * v0;
                                     v1 = (v1 > 0.f) ? v1 : 0.01f * v1; }
                else if (act == 3) { v0 = tanhf(v0); v1 = tanhf(v1); }
                *reinterpret_cast<float2*>(&C[(size_t)gr * N + gc]) = make_float2(v0, v1);
            }
        }
    }
}

// ------------------------- launcher -------------------------
extern "C" void kernel_launch(void* const* d_in, const int* in_sizes, int n_in,
                              void* d_out, int out_size) {
    (void)in_sizes; (void)n_in; (void)out_size;
    const float* x     = (const float*)d_in[0];
    const int*   edges = (const int*)d_in[1];
    const int*   seeds = (const int*)d_in[2];
    const float* noise = (const float*)d_in[3];
    const float* V1    = (const float*)d_in[4];
    const float* C1    = (const float*)d_in[5];
    const float* V2    = (const float*)d_in[6];
    const float* C2    = (const float*)d_in[7];
    const float* W_lin = (const float*)d_in[8];
    const float* b_lin = (const float*)d_in[9];
    const float* Wd1   = (const float*)d_in[10];
    const float* bd1   = (const float*)d_in[11];
    const float* Wd2   = (const float*)d_in[12];
    const float* bd2   = (const float*)d_in[13];
    const float* Wd3   = (const float*)d_in[14];
    const float* bd3   = (const float*)d_in[15];
    const float* Wf1   = (const float*)d_in[16];
    const float* bf1   = (const float*)d_in[17];
    const float* Wf2   = (const float*)d_in[18];
    const float* bf2   = (const float*)d_in[19];
    const float* Wf3   = (const float*)d_in[20];
    const float* bf3   = (const float*)d_in[21];
    float* out = (float*)d_out;

    void *pDeg, *pA, *pBcat, *pIs, *pH1, *pSA, *pH2, *pHs, *pD1, *pD2, *pF1, *pF2;
    cudaGetSymbolAddress(&pDeg, g_deg);
    cudaGetSymbolAddress(&pA, g_A);
    cudaGetSymbolAddress(&pBcat, g_Bcat);
    cudaGetSymbolAddress(&pIs, g_isseed);
    cudaGetSymbolAddress(&pH1, g_h1);
    cudaGetSymbolAddress(&pSA, g_sA);
    cudaGetSymbolAddress(&pH2, g_h2);
    cudaGetSymbolAddress(&pHs, g_hs);
    cudaGetSymbolAddress(&pD1, g_D1);
    cudaGetSymbolAddress(&pD2, g_D2);
    cudaGetSymbolAddress(&pF1, g_F1);
    cudaGetSymbolAddress(&pF2, g_F2);
    float* dBcat = (float*)pBcat;
    float* dH1   = (float*)pH1;
    float* dSA   = (float*)pSA;
    float* dH2   = (float*)pH2;
    float* dHs   = (float*)pHs;
    float* dD1   = (float*)pD1;
    float* dD2   = (float*)pD2;
    float* dF1   = (float*)pF1;
    float* dF2   = (float*)pF2;

    // zero accumulators + flags
    cudaMemsetAsync(pDeg, 0, sizeof(float) * RR * NN);
    cudaMemsetAsync(pA, 0, sizeof(float) * (size_t)RR * NN * 64);
    cudaMemsetAsync(pIs, 0, NN);

    const int scatterBlocks = (RR * EE * 16 + 255) / 256;

    k_seedflag<<<(SS + 255) / 256, 256>>>(seeds);
    k_deg<<<(RR * EE + 255) / 256, 256>>>(edges);
    k_invdeg<<<(RR * NN + 255) / 256, 256>>>();

    // ---- conv layer 1 (full graph) ----
    k_scatterA<<<scatterBlocks, 256>>>(x, edges, 0);
    k_combine1<<<(NN * 16 + 255) / 256, 256>>>(C1);
    mma_gemm<64, 32, 32><<<dim3(1, (NN + 127) / 128, 1), 256>>>(
        dBcat, 0, V1, 0, nullptr, 0, 0, dH1, 0, NN, 64, 128, 1);

    // ---- conv layer 2 (seed destinations only) ----
    k_zeroAseed<<<(SS * RR * 16 + 255) / 256, 256>>>(seeds);
    k_scatterA<<<scatterBlocks, 256>>>(dH1, edges, 1);
    k_combine2<<<(SS * 16 + 255) / 256, 256>>>(C2, seeds);
    mma_gemm<64, 32, 32><<<dim3(1, SS / 128, 1), 256>>>(
        dSA, 0, V2, 0, nullptr, 0, 0, dH2, 0, SS, 64, 128, 1);

    // ---- linear + leaky + noise at seeds ----
    mma_gemm<64, 32, 32><<<dim3(1, SS / 128, 1), 256>>>(
        dH2, 0, W_lin, 0, b_lin, 0, 1, dHs, 0, SS, 64, 64, 2);
    k_addnoise<<<(SS * 64 + 255) / 256, 256>>>(noise, seeds);

    // ---- d branch ----
    mma_gemm<128, 64, 32><<<dim3(2, SS / 128, PP), 256>>>(
        dHs, 0, Wd1, (size_t)64 * 256, bd1, 256, 1, dD1, (size_t)SS * 256, SS, 256, 64, 2);
    mma_gemm<64, 32, 32><<<dim3(1, SS / 128, PP), 256>>>(
        dD1, (size_t)SS * 256, Wd2, (size_t)256 * 32, bd2, 32, 1, dD2, (size_t)SS * 32, SS, 32, 256, 2);
    k_d3<<<(PP * SS + 255) / 256, 256>>>(Wd3, bd3, out);

    // ---- f branch ----
    mma_gemm<128, 64, 32><<<dim3(2, SS / 128, PP), 256>>>(
        dHs, 0, Wf1, (size_t)64 * 256, bf1, 256, 1, dF1, (size_t)SS * 256, SS, 256, 64, 1);
    mma_gemm<128, 64, 64><<<dim3(16, SS / 128, PP), 128>>>(
        dF1, (size_t)SS * 256, Wf2, (size_t)256 * 2048, bf2, 2048, 1, dF2, (size_t)SS * 2048, SS, 2048, 256, 1);
    mma_gemm<128, 64, 64><<<dim3(3, SS / 128, PP), 128>>>(
        dF2, (size_t)SS * 2048, Wf3, (size_t)2048 * 320, bf3, 320, 1, out + PP * SS, (size_t)SS * 320, SS, 320, 2048, 3);
}

// round 6
// speedup vs baseline: 2.5129x; 1.0053x over previous
#include <cuda_runtime.h>
#include <cstdint>
#include <cstddef>

#define NN 100000
#define RR 4
#define EE 300000
#define HH 64
#define SS 4096
#define PP 2

// ------------------------- scratch (static device globals; no allocs) -------------------------
__device__ float g_deg[RR * NN];                 // degree, then in-place inverse degree
__device__ float g_A[(size_t)RR * NN * 64];      // per-relation unweighted aggregation
__device__ float g_Bcat[(size_t)NN * 128];       // combined [B0 | B1] per node
__device__ float g_h1[(size_t)NN * HH];          // layer-1 output
__device__ unsigned char g_isseed[NN];
__device__ unsigned char g_need[NN];             // node is src of a seed-destined edge
__device__ int2 g_se[(size_t)RR * EE];           // compacted seed-destined edges per relation
__device__ int  g_cnt[RR];
__device__ float g_sA[SS * 128];                 // combined layer-2 features at seeds
__device__ float g_h2[SS * HH];
__device__ float g_hs[SS * HH];
__device__ float g_D1[PP * SS * 256];
__device__ float g_D2[PP * SS * 32];
__device__ float g_F1[PP * SS * 256];
__device__ float g_F2[(size_t)PP * SS * 2048];

// ------------------------- helpers -------------------------
__device__ __forceinline__ void red_add4(float* p, float a, float b, float c, float d) {
    asm volatile("red.global.add.v4.f32 [%0], {%1,%2,%3,%4};" ::
                 "l"(p), "f"(a), "f"(b), "f"(c), "f"(d) : "memory");
}

__device__ __forceinline__ uint32_t f2tf(float x) {
    uint32_t u;
    asm("cvt.rna.tf32.f32 %0, %1;" : "=r"(u) : "f"(x));
    return u;
}

__device__ __forceinline__ void mma_tf32(float* c, const uint32_t* a, const uint32_t* b) {
    asm volatile(
        "mma.sync.aligned.m16n8k8.row.col.f32.tf32.tf32.f32 "
        "{%0,%1,%2,%3},{%4,%5,%6,%7},{%8,%9},{%0,%1,%2,%3};"
        : "+f"(c[0]), "+f"(c[1]), "+f"(c[2]), "+f"(c[3])
        : "r"(a[0]), "r"(a[1]), "r"(a[2]), "r"(a[3]), "r"(b[0]), "r"(b[1]));
}

// ------------------------- small kernels -------------------------
__global__ void k_seedflag(const int* __restrict__ seeds) {
    int i = blockIdx.x * blockDim.x + threadIdx.x;
    if (i < SS) g_isseed[seeds[i]] = 1;
}

// single edge pass: degree + compact seed-destined edges + mark needed sources
__global__ void k_edgepass(const int* __restrict__ edges) {
    int e = blockIdx.x * blockDim.x + threadIdx.x;
    if (e >= RR * EE) return;
    int r = e / EE;
    int2 ed = reinterpret_cast<const int2*>(edges)[e];   // (src, dst)
    atomicAdd(&g_deg[r * NN + ed.y], 1.0f);
    if (g_isseed[ed.y]) {
        g_need[ed.x] = 1;
        int pos = atomicAdd(&g_cnt[r], 1);
        g_se[(size_t)r * EE + pos] = ed;
    }
}

__global__ void k_invdeg() {
    int i = blockIdx.x * blockDim.x + threadIdx.x;
    if (i < RR * NN) g_deg[i] = 1.0f / fmaxf(g_deg[i], 1.0f);
}

// zero A rows for needed nodes only
__global__ void k_zeroAneed() {
    int idx = blockIdx.x * blockDim.x + threadIdx.x;
    if (idx >= NN * 16) return;
    int n = idx >> 4, i4 = idx & 15;
    if (!g_need[n]) return;
#pragma unroll
    for (int r = 0; r < RR; r++)
        *reinterpret_cast<float4*>(&g_A[((size_t)r * NN + n) * 64 + i4 * 4]) =
            make_float4(0.f, 0.f, 0.f, 0.f);
}

// layer-1 scatter: A[r][dst] += x[src] for edges whose dst is needed. 16 lanes/edge.
__global__ void k_scatterA(const float* __restrict__ h, const int* __restrict__ edges) {
    int gid = blockIdx.x * blockDim.x + threadIdx.x;
    int e = gid >> 4;
    if (e >= RR * EE) return;
    int l = gid & 15;
    int r = e / EE;
    int2 ed = reinterpret_cast<const int2*>(edges)[e];   // (src, dst)
    if (!g_need[ed.y]) return;
    float4 xv = *reinterpret_cast<const float4*>(&h[(size_t)ed.x * 64 + l * 4]);
    red_add4(&g_A[((size_t)r * NN + ed.y) * 64 + l * 4], xv.x, xv.y, xv.z, xv.w);
}

// layer-2 scatter over the compacted seed-edge list. 16 lanes/edge.
__global__ void k_scatterList(const float* __restrict__ h) {
    int gid = blockIdx.x * blockDim.x + threadIdx.x;
    int e = gid >> 4;
    if (e >= RR * EE) return;
    int r = e / EE;
    int local = e - r * EE;
    if (local >= g_cnt[r]) return;
    int l = gid & 15;
    int2 ed = g_se[(size_t)r * EE + local];
    float4 xv = *reinterpret_cast<const float4*>(&h[(size_t)ed.x * 64 + l * 4]);
    red_add4(&g_A[((size_t)r * NN + ed.y) * 64 + l * 4], xv.x, xv.y, xv.z, xv.w);
}

// Bcat[n, b*64+i] = sum_r C[r,b] * invdeg_r[n] * A[r][n][i]   (needed nodes only)
__global__ void k_combine1(const float* __restrict__ Cmat) {
    int idx = blockIdx.x * blockDim.x + threadIdx.x;
    if (idx >= NN * 16) return;
    int n = idx >> 4, i4 = idx & 15;
    if (!g_need[n]) return;
    float4 o0 = make_float4(0.f, 0.f, 0.f, 0.f);
    float4 o1 = make_float4(0.f, 0.f, 0.f, 0.f);
#pragma unroll
    for (int r = 0; r < RR; r++) {
        float inv = __ldg(&g_deg[r * NN + n]);
        float c0 = __ldg(&Cmat[r * 2 + 0]) * inv;
        float c1 = __ldg(&Cmat[r * 2 + 1]) * inv;
        float4 a = *reinterpret_cast<const float4*>(&g_A[((size_t)r * NN + n) * 64 + i4 * 4]);
        o0.x += c0 * a.x; o0.y += c0 * a.y; o0.z += c0 * a.z; o0.w += c0 * a.w;
        o1.x += c1 * a.x; o1.y += c1 * a.y; o1.z += c1 * a.z; o1.w += c1 * a.w;
    }
    *reinterpret_cast<float4*>(&g_Bcat[(size_t)n * 128 + i4 * 4]) = o0;
    *reinterpret_cast<float4*>(&g_Bcat[(size_t)n * 128 + 64 + i4 * 4]) = o1;
}

// zero A rows for seed nodes only (thread per (s, r, i4))
__global__ void k_zeroAseed(const int* __restrict__ seeds) {
    int idx = blockIdx.x * blockDim.x + threadIdx.x;
    if (idx >= SS * RR * 16) return;
    int s = idx >> 6;
    int r = (idx >> 4) & 3;
    int i4 = idx & 15;
    int node = seeds[s];
    *reinterpret_cast<float4*>(&g_A[((size_t)r * NN + node) * 64 + i4 * 4]) =
        make_float4(0.f, 0.f, 0.f, 0.f);
}

// sA[s, b*64+i] = sum_r C2[r,b] * invdeg_r[node] * A[r][node][i]  (16 threads per seed)
__global__ void k_combine2(const float* __restrict__ Cmat, const int* __restrict__ seeds) {
    int idx = blockIdx.x * blockDim.x + threadIdx.x;
    if (idx >= SS * 16) return;
    int s = idx >> 4, i4 = idx & 15;
    int n = seeds[s];
    float4 o0 = make_float4(0.f, 0.f, 0.f, 0.f);
    float4 o1 = make_float4(0.f, 0.f, 0.f, 0.f);
#pragma unroll
    for (int r = 0; r < RR; r++) {
        float inv = __ldg(&g_deg[r * NN + n]);
        float c0 = __ldg(&Cmat[r * 2 + 0]) * inv;
        float c1 = __ldg(&Cmat[r * 2 + 1]) * inv;
        float4 a = *reinterpret_cast<const float4*>(&g_A[((size_t)r * NN + n) * 64 + i4 * 4]);
        o0.x += c0 * a.x; o0.y += c0 * a.y; o0.z += c0 * a.z; o0.w += c0 * a.w;
        o1.x += c1 * a.x; o1.y += c1 * a.y; o1.z += c1 * a.z; o1.w += c1 * a.w;
    }
    *reinterpret_cast<float4*>(&g_sA[(size_t)s * 128 + i4 * 4]) = o0;
    *reinterpret_cast<float4*>(&g_sA[(size_t)s * 128 + 64 + i4 * 4]) = o1;
}

__global__ void k_addnoise(const float* __restrict__ noise, const int* __restrict__ seeds) {
    int i = blockIdx.x * blockDim.x + threadIdx.x;
    if (i >= SS * 64) return;
    int s = i >> 6;
    g_hs[i] += noise[(size_t)seeds[s] * 64 + (i & 63)];
}

__global__ void k_d3(const float* __restrict__ Wd3, const float* __restrict__ bd3,
                     float* __restrict__ out) {
    int i = blockIdx.x * blockDim.x + threadIdx.x;
    if (i >= PP * SS) return;
    int p = i / SS;
    const float* v = &g_D2[(size_t)i * 32];
    const float* w = &Wd3[p * 32];
    float sum = bd3[p];
#pragma unroll
    for (int k = 0; k < 32; k++) sum += v[k] * w[k];
    out[i] = fmaxf(sum, 0.0f);
}

// ------------------------- tf32 tensor-core GEMM: C = act(A@W + bias) -------------------------
// A: [M,K] row-major. W: [K,N] row-major. C: [M,N] row-major. Batched over blockIdx.z.
// Requires K % 16 == 0, N % 4 == 0. act: 0=none, 1=relu, 2=leaky(0.01), 3=tanh.
// BM=128, BK=16. Thread count = 32 * (BM/WM) * (BN/WN).
template <int BN, int WM, int WN>
__global__ __launch_bounds__(32 * (128 / WM) * (BN / WN), 1)
void mma_gemm(const float* __restrict__ A, size_t strA,
              const float* __restrict__ W, size_t strW,
              const float* __restrict__ bias, size_t strBias, int hasBias,
              float* __restrict__ C, size_t strC,
              int M, int N, int K, int act) {
    constexpr int BM = 128, BK = 16;
    constexpr int MT = WM / 16, NT = WN / 8;
    constexpr int WARPS_M = BM / WM;
    constexpr int NTH = 32 * WARPS_M * (BN / WN);
    constexpr int SKA = BK + 4;            // 20: conflict-free A-fragment loads
    constexpr int SKB = BN + 8;            // conflict-free B-fragment loads
    constexpr int A4 = BM * BK / 4 / NTH;  // float4 A loads per thread
    constexpr int B4 = BK * BN / 4 / NTH;  // float4 B loads per thread

    __shared__ uint32_t As[2][BM * SKA];
    __shared__ uint32_t Bs[2][BK * SKB];

    int tid = threadIdx.x, lane = tid & 31, wid = tid >> 5;
    int g = lane >> 2, t4 = lane & 3;
    int wm = (wid % WARPS_M) * WM;
    int wn = (wid / WARPS_M) * WN;

    int p = blockIdx.z;
    A += (size_t)p * strA;
    W += (size_t)p * strW;
    C += (size_t)p * strC;
    const float* bp = hasBias ? (bias + (size_t)p * strBias) : nullptr;

    int row0 = blockIdx.y * BM, col0 = blockIdx.x * BN;

    float acc[MT][NT][4];
#pragma unroll
    for (int mt = 0; mt < MT; mt++)
#pragma unroll
        for (int nt = 0; nt < NT; nt++)
#pragma unroll
            for (int i = 0; i < 4; i++) acc[mt][nt][i] = 0.f;

    float4 va[A4], vb[B4];

    auto ldg_tile = [&](int kt) {
#pragma unroll
        for (int i = 0; i < A4; i++) {
            int idx = tid + i * NTH;
            int r = idx >> 2;                 // BK/4 = 4 float4 per A row
            int c4 = (idx & 3) * 4;
            int gr = row0 + r;
            va[i] = (gr < M) ? *reinterpret_cast<const float4*>(&A[(size_t)gr * K + kt + c4])
                             : make_float4(0.f, 0.f, 0.f, 0.f);
        }
#pragma unroll
        for (int i = 0; i < B4; i++) {
            int idx = tid + i * NTH;
            int r = idx / (BN / 4);
            int c4 = (idx % (BN / 4)) * 4;
            int gc = col0 + c4;
            vb[i] = (gc < N) ? *reinterpret_cast<const float4*>(&W[(size_t)(kt + r) * N + gc])
                             : make_float4(0.f, 0.f, 0.f, 0.f);
        }
    };
    auto sts_tile = [&](int buf) {
#pragma unroll
        for (int i = 0; i < A4; i++) {
            int idx = tid + i * NTH;
            int r = idx >> 2;
            int c4 = (idx & 3) * 4;
            uint4 u = make_uint4(f2tf(va[i].x), f2tf(va[i].y), f2tf(va[i].z), f2tf(va[i].w));
            *reinterpret_cast<uint4*>(&As[buf][r * SKA + c4]) = u;
        }
#pragma unroll
        for (int i = 0; i < B4; i++) {
            int idx = tid + i * NTH;
            int r = idx / (BN / 4);
            int c4 = (idx % (BN / 4)) * 4;
            uint4 u = make_uint4(f2tf(vb[i].x), f2tf(vb[i].y), f2tf(vb[i].z), f2tf(vb[i].w));
            *reinterpret_cast<uint4*>(&Bs[buf][r * SKB + c4]) = u;
        }
    };

    int ntiles = K / BK;
    ldg_tile(0);
    sts_tile(0);
    __syncthreads();
    int cur = 0;

    for (int kt = 0; kt < ntiles; kt++) {
        if (kt + 1 < ntiles) ldg_tile((kt + 1) * BK);
#pragma unroll
        for (int ks = 0; ks < BK; ks += 8) {
            uint32_t af[MT][4], bf[NT][2];
#pragma unroll
            for (int mt = 0; mt < MT; mt++) {
                const uint32_t* base = &As[cur][(wm + mt * 16) * SKA + ks + t4];
                af[mt][0] = base[g * SKA];
                af[mt][1] = base[(g + 8) * SKA];
                af[mt][2] = base[g * SKA + 4];
                af[mt][3] = base[(g + 8) * SKA + 4];
            }
#pragma unroll
            for (int nt = 0; nt < NT; nt++) {
                const uint32_t* base = &Bs[cur][(ks + t4) * SKB + wn + nt * 8 + g];
                bf[nt][0] = base[0];
                bf[nt][1] = base[4 * SKB];
            }
#pragma unroll
            for (int mt = 0; mt < MT; mt++)
#pragma unroll
                for (int nt = 0; nt < NT; nt++)
                    mma_tf32(acc[mt][nt], af[mt], bf[nt]);
        }
        if (kt + 1 < ntiles) {
            sts_tile(cur ^ 1);
            __syncthreads();
            cur ^= 1;
        }
    }

    // epilogue
#pragma unroll
    for (int mt = 0; mt < MT; mt++) {
#pragma unroll
        for (int nt = 0; nt < NT; nt++) {
            int gc = col0 + wn + nt * 8 + t4 * 2;
            if (gc >= N) continue;
            float bias0 = bp ? bp[gc] : 0.f;
            float bias1 = bp ? bp[gc + 1] : 0.f;
#pragma unroll
            for (int h = 0; h < 2; h++) {
                int gr = row0 + wm + mt * 16 + g + h * 8;
                if (gr >= M) continue;
                float v0 = acc[mt][nt][2 * h + 0] + bias0;
                float v1 = acc[mt][nt][2 * h + 1] + bias1;
                if (act == 1)      { v0 = fmaxf(v0, 0.f); v1 = fmaxf(v1, 0.f); }
                else if (act == 2) { v0 = (v0 > 0.f) ? v0 : 0.01f * v0;
                                     v1 = (v1 > 0.f) ? v1 : 0.01f * v1; }
                else if (act == 3) { v0 = tanhf(v0); v1 = tanhf(v1); }
                *reinterpret_cast<float2*>(&C[(size_t)gr * N + gc]) = make_float2(v0, v1);
            }
        }
    }
}

// ------------------------- launcher -------------------------
extern "C" void kernel_launch(void* const* d_in, const int* in_sizes, int n_in,
                              void* d_out, int out_size) {
    (void)in_sizes; (void)n_in; (void)out_size;
    const float* x     = (const float*)d_in[0];
    const int*   edges = (const int*)d_in[1];
    const int*   seeds = (const int*)d_in[2];
    const float* noise = (const float*)d_in[3];
    const float* V1    = (const float*)d_in[4];
    const float* C1    = (const float*)d_in[5];
    const float* V2    = (const float*)d_in[6];
    const float* C2    = (const float*)d_in[7];
    const float* W_lin = (const float*)d_in[8];
    const float* b_lin = (const float*)d_in[9];
    const float* Wd1   = (const float*)d_in[10];
    const float* bd1   = (const float*)d_in[11];
    const float* Wd2   = (const float*)d_in[12];
    const float* bd2   = (const float*)d_in[13];
    const float* Wd3   = (const float*)d_in[14];
    const float* bd3   = (const float*)d_in[15];
    const float* Wf1   = (const float*)d_in[16];
    const float* bf1   = (const float*)d_in[17];
    const float* Wf2   = (const float*)d_in[18];
    const float* bf2   = (const float*)d_in[19];
    const float* Wf3   = (const float*)d_in[20];
    const float* bf3   = (const float*)d_in[21];
    float* out = (float*)d_out;

    void *pDeg, *pIs, *pNeed, *pCnt, *pBcat, *pH1, *pSA, *pH2, *pHs, *pD1, *pD2, *pF1, *pF2;
    cudaGetSymbolAddress(&pDeg, g_deg);
    cudaGetSymbolAddress(&pIs, g_isseed);
    cudaGetSymbolAddress(&pNeed, g_need);
    cudaGetSymbolAddress(&pCnt, g_cnt);
    cudaGetSymbolAddress(&pBcat, g_Bcat);
    cudaGetSymbolAddress(&pH1, g_h1);
    cudaGetSymbolAddress(&pSA, g_sA);
    cudaGetSymbolAddress(&pH2, g_h2);
    cudaGetSymbolAddress(&pHs, g_hs);
    cudaGetSymbolAddress(&pD1, g_D1);
    cudaGetSymbolAddress(&pD2, g_D2);
    cudaGetSymbolAddress(&pF1, g_F1);
    cudaGetSymbolAddress(&pF2, g_F2);
    float* dBcat = (float*)pBcat;
    float* dH1   = (float*)pH1;
    float* dSA   = (float*)pSA;
    float* dH2   = (float*)pH2;
    float* dHs   = (float*)pHs;
    float* dD1   = (float*)pD1;
    float* dD2   = (float*)pD2;
    float* dF1   = (float*)pF1;
    float* dF2   = (float*)pF2;

    // zero small accumulators + flags (A zeroed selectively after need[] is known)
    cudaMemsetAsync(pDeg, 0, sizeof(float) * RR * NN);
    cudaMemsetAsync(pIs, 0, NN);
    cudaMemsetAsync(pNeed, 0, NN);
    cudaMemsetAsync(pCnt, 0, sizeof(int) * RR);

    const int scatterBlocks = (RR * EE * 16 + 255) / 256;

    k_seedflag<<<(SS + 255) / 256, 256>>>(seeds);
    k_edgepass<<<(RR * EE + 255) / 256, 256>>>(edges);
    k_invdeg<<<(RR * NN + 255) / 256, 256>>>();

    // ---- conv layer 1 (restricted to sources of seed-destined edges) ----
    k_zeroAneed<<<(NN * 16 + 255) / 256, 256>>>();
    k_scatterA<<<scatterBlocks, 256>>>(x, edges);
    k_combine1<<<(NN * 16 + 255) / 256, 256>>>(C1);
    mma_gemm<64, 32, 32><<<dim3(1, (NN + 127) / 128, 1), 256>>>(
        dBcat, 0, V1, 0, nullptr, 0, 0, dH1, 0, NN, 64, 128, 1);

    // ---- conv layer 2 (compacted seed-edge list) ----
    k_zeroAseed<<<(SS * RR * 16 + 255) / 256, 256>>>(seeds);
    k_scatterList<<<scatterBlocks, 256>>>(dH1);
    k_combine2<<<(SS * 16 + 255) / 256, 256>>>(C2, seeds);
    mma_gemm<64, 32, 32><<<dim3(1, SS / 128, 1), 256>>>(
        dSA, 0, V2, 0, nullptr, 0, 0, dH2, 0, SS, 64, 128, 1);

    // ---- linear + leaky + noise at seeds ----
    mma_gemm<64, 32, 32><<<dim3(1, SS / 128, 1), 256>>>(
        dH2, 0, W_lin, 0, b_lin, 0, 1, dHs, 0, SS, 64, 64, 2);
    k_addnoise<<<(SS * 64 + 255) / 256, 256>>>(noise, seeds);

    // ---- d branch ----
    mma_gemm<128, 64, 32><<<dim3(2, SS / 128, PP), 256>>>(
        dHs, 0, Wd1, (size_t)64 * 256, bd1, 256, 1, dD1, (size_t)SS * 256, SS, 256, 64, 2);
    mma_gemm<64, 32, 32><<<dim3(1, SS / 128, PP), 256>>>(
        dD1, (size_t)SS * 256, Wd2, (size_t)256 * 32, bd2, 32, 1, dD2, (size_t)SS * 32, SS, 32, 256, 2);
    k_d3<<<(PP * SS + 255) / 256, 256>>>(Wd3, bd3, out);

    // ---- f branch ----
    mma_gemm<128, 64, 32><<<dim3(2, SS / 128, PP), 256>>>(
        dHs, 0, Wf1, (size_t)64 * 256, bf1, 256, 1, dF1, (size_t)SS * 256, SS, 256, 64, 1);
    mma_gemm<128, 64, 64><<<dim3(16, SS / 128, PP), 128>>>(
        dF1, (size_t)SS * 256, Wf2, (size_t)256 * 2048, bf2, 2048, 1, dF2, (size_t)SS * 2048, SS, 2048, 256, 1);
    mma_gemm<128, 64, 64><<<dim3(3, SS / 128, PP), 128>>>(
        dF2, (size_t)SS * 2048, Wf3, (size_t)2048 * 320, bf3, 320, 1, out + PP * SS, (size_t)SS * 320, SS, 320, 2048, 3);
}

// round 7
// speedup vs baseline: 2.5556x; 1.0170x over previous
#include <cuda_runtime.h>
#include <cstdint>
#include <cstddef>

#define NN 100000
#define RR 4
#define EE 300000
#define HH 64
#define SS 4096
#define PP 2

// ------------------------- scratch (static device globals; no allocs) -------------------------
__device__ float g_deg[RR * NN];                 // degree, then in-place inverse degree
__device__ float g_A[(size_t)RR * NN * 64];      // per-relation unweighted aggregation
__device__ float g_Bcat[(size_t)NN * 128];       // combined [B0 | B1] per node
__device__ float g_h1[(size_t)NN * HH];          // layer-1 output
__device__ unsigned char g_isseed[NN];
__device__ unsigned char g_need[NN];             // node is src of a seed-destined edge
__device__ int2 g_se[(size_t)RR * EE];           // compacted seed-destined edges per relation
__device__ int  g_cnt[RR];
__device__ float g_sA[SS * 128];                 // combined layer-2 features at seeds
__device__ float g_h2[SS * HH];
__device__ float g_hs[SS * HH];
__device__ float g_D1[PP * SS * 256];
__device__ float g_D2[PP * SS * 32];
__device__ float g_F1[PP * SS * 256];
__device__ float g_F2[(size_t)PP * SS * 2048];

// ------------------------- helpers -------------------------
__device__ __forceinline__ void red_add4(float* p, float a, float b, float c, float d) {
    asm volatile("red.global.add.v4.f32 [%0], {%1,%2,%3,%4};" ::
                 "l"(p), "f"(a), "f"(b), "f"(c), "f"(d) : "memory");
}

__device__ __forceinline__ uint32_t f2tf(float x) {
    uint32_t u;
    asm("cvt.rna.tf32.f32 %0, %1;" : "=r"(u) : "f"(x));
    return u;
}

__device__ __forceinline__ void mma_tf32(float* c, const uint32_t* a, const uint32_t* b) {
    asm volatile(
        "mma.sync.aligned.m16n8k8.row.col.f32.tf32.tf32.f32 "
        "{%0,%1,%2,%3},{%4,%5,%6,%7},{%8,%9},{%0,%1,%2,%3};"
        : "+f"(c[0]), "+f"(c[1]), "+f"(c[2]), "+f"(c[3])
        : "r"(a[0]), "r"(a[1]), "r"(a[2]), "r"(a[3]), "r"(b[0]), "r"(b[1]));
}

// ------------------------- small kernels -------------------------
__global__ void k_seedflag(const int* __restrict__ seeds) {
    int i = blockIdx.x * blockDim.x + threadIdx.x;
    if (i < SS) g_isseed[seeds[i]] = 1;
}

// single edge pass: degree + compact seed-destined edges + mark needed sources
__global__ void k_edgepass(const int* __restrict__ edges) {
    int e = blockIdx.x * blockDim.x + threadIdx.x;
    if (e >= RR * EE) return;
    int r = e / EE;
    int2 ed = reinterpret_cast<const int2*>(edges)[e];   // (src, dst)
    atomicAdd(&g_deg[r * NN + ed.y], 1.0f);
    if (g_isseed[ed.y]) {
        g_need[ed.x] = 1;
        int pos = atomicAdd(&g_cnt[r], 1);
        g_se[(size_t)r * EE + pos] = ed;
    }
}

__global__ void k_invdeg() {
    int i = blockIdx.x * blockDim.x + threadIdx.x;
    if (i < RR * NN) g_deg[i] = 1.0f / fmaxf(g_deg[i], 1.0f);
}

// zero A rows for needed nodes only
__global__ void k_zeroAneed() {
    int idx = blockIdx.x * blockDim.x + threadIdx.x;
    if (idx >= NN * 16) return;
    int n = idx >> 4, i4 = idx & 15;
    if (!g_need[n]) return;
#pragma unroll
    for (int r = 0; r < RR; r++)
        *reinterpret_cast<float4*>(&g_A[((size_t)r * NN + n) * 64 + i4 * 4]) =
            make_float4(0.f, 0.f, 0.f, 0.f);
}

// layer-1 scatter: A[r][dst] += x[src] for edges whose dst is needed. 16 lanes/edge.
__global__ void k_scatterA(const float* __restrict__ h, const int* __restrict__ edges) {
    int gid = blockIdx.x * blockDim.x + threadIdx.x;
    int e = gid >> 4;
    if (e >= RR * EE) return;
    int l = gid & 15;
    int r = e / EE;
    int2 ed = reinterpret_cast<const int2*>(edges)[e];   // (src, dst)
    if (!g_need[ed.y]) return;
    float4 xv = *reinterpret_cast<const float4*>(&h[(size_t)ed.x * 64 + l * 4]);
    red_add4(&g_A[((size_t)r * NN + ed.y) * 64 + l * 4], xv.x, xv.y, xv.z, xv.w);
}

// layer-2 scatter over the compacted seed-edge lists (grid-stride). 16 lanes/edge.
__global__ void k_scatterList(const float* __restrict__ h) {
    int gid = blockIdx.x * blockDim.x + threadIdx.x;
    int l = gid & 15;
    int chunk = gid >> 4;
    int nchunks = (gridDim.x * blockDim.x) >> 4;
#pragma unroll
    for (int r = 0; r < RR; r++) {
        int c = g_cnt[r];
        for (int e = chunk; e < c; e += nchunks) {
            int2 ed = g_se[(size_t)r * EE + e];
            float4 xv = *reinterpret_cast<const float4*>(&h[(size_t)ed.x * 64 + l * 4]);
            red_add4(&g_A[((size_t)r * NN + ed.y) * 64 + l * 4], xv.x, xv.y, xv.z, xv.w);
        }
    }
}

// Bcat[n, b*64+i] = sum_r C[r,b] * invdeg_r[n] * A[r][n][i]   (needed nodes only)
__global__ void k_combine1(const float* __restrict__ Cmat) {
    int idx = blockIdx.x * blockDim.x + threadIdx.x;
    if (idx >= NN * 16) return;
    int n = idx >> 4, i4 = idx & 15;
    if (!g_need[n]) return;
    float4 o0 = make_float4(0.f, 0.f, 0.f, 0.f);
    float4 o1 = make_float4(0.f, 0.f, 0.f, 0.f);
#pragma unroll
    for (int r = 0; r < RR; r++) {
        float inv = __ldg(&g_deg[r * NN + n]);
        float c0 = __ldg(&Cmat[r * 2 + 0]) * inv;
        float c1 = __ldg(&Cmat[r * 2 + 1]) * inv;
        float4 a = *reinterpret_cast<const float4*>(&g_A[((size_t)r * NN + n) * 64 + i4 * 4]);
        o0.x += c0 * a.x; o0.y += c0 * a.y; o0.z += c0 * a.z; o0.w += c0 * a.w;
        o1.x += c1 * a.x; o1.y += c1 * a.y; o1.z += c1 * a.z; o1.w += c1 * a.w;
    }
    *reinterpret_cast<float4*>(&g_Bcat[(size_t)n * 128 + i4 * 4]) = o0;
    *reinterpret_cast<float4*>(&g_Bcat[(size_t)n * 128 + 64 + i4 * 4]) = o1;
}

// zero A rows for seed nodes only (thread per (s, r, i4))
__global__ void k_zeroAseed(const int* __restrict__ seeds) {
    int idx = blockIdx.x * blockDim.x + threadIdx.x;
    if (idx >= SS * RR * 16) return;
    int s = idx >> 6;
    int r = (idx >> 4) & 3;
    int i4 = idx & 15;
    int node = seeds[s];
    *reinterpret_cast<float4*>(&g_A[((size_t)r * NN + node) * 64 + i4 * 4]) =
        make_float4(0.f, 0.f, 0.f, 0.f);
}

// sA[s, b*64+i] = sum_r C2[r,b] * invdeg_r[node] * A[r][node][i]  (16 threads per seed)
__global__ void k_combine2(const float* __restrict__ Cmat, const int* __restrict__ seeds) {
    int idx = blockIdx.x * blockDim.x + threadIdx.x;
    if (idx >= SS * 16) return;
    int s = idx >> 4, i4 = idx & 15;
    int n = seeds[s];
    float4 o0 = make_float4(0.f, 0.f, 0.f, 0.f);
    float4 o1 = make_float4(0.f, 0.f, 0.f, 0.f);
#pragma unroll
    for (int r = 0; r < RR; r++) {
        float inv = __ldg(&g_deg[r * NN + n]);
        float c0 = __ldg(&Cmat[r * 2 + 0]) * inv;
        float c1 = __ldg(&Cmat[r * 2 + 1]) * inv;
        float4 a = *reinterpret_cast<const float4*>(&g_A[((size_t)r * NN + n) * 64 + i4 * 4]);
        o0.x += c0 * a.x; o0.y += c0 * a.y; o0.z += c0 * a.z; o0.w += c0 * a.w;
        o1.x += c1 * a.x; o1.y += c1 * a.y; o1.z += c1 * a.z; o1.w += c1 * a.w;
    }
    *reinterpret_cast<float4*>(&g_sA[(size_t)s * 128 + i4 * 4]) = o0;
    *reinterpret_cast<float4*>(&g_sA[(size_t)s * 128 + 64 + i4 * 4]) = o1;
}

__global__ void k_d3(const float* __restrict__ Wd3, const float* __restrict__ bd3,
                     float* __restrict__ out) {
    int i = blockIdx.x * blockDim.x + threadIdx.x;
    if (i >= PP * SS) return;
    int p = i / SS;
    const float* v = &g_D2[(size_t)i * 32];
    const float* w = &Wd3[p * 32];
    float sum = bd3[p];
#pragma unroll
    for (int k = 0; k < 32; k++) sum += v[k] * w[k];
    out[i] = fmaxf(sum, 0.0f);
}

// ------------------------- tf32 tensor-core GEMM: C = act(A@W + bias) -------------------------
// A: [M,K] row-major. W: [K,N] row-major. C: [M,N] row-major. Batched over blockIdx.z.
// Requires K % 16 == 0, N % 4 == 0. act: 0=none, 1=relu, 2=leaky(0.01), 3=tanh.
// Fragment-native shared layouts: A-frag = 1 LDS.128, B-frag = 1 LDS.64.
// If gnoise != null: out += gnoise[gseeds[row]*64 + col] after activation (needs N<=64 use).
template <int BN, int WM, int WN, int MINB>
__global__ __launch_bounds__(32 * (128 / WM) * (BN / WN), MINB)
void mma_gemm(const float* __restrict__ A, size_t strA,
              const float* __restrict__ W, size_t strW,
              const float* __restrict__ bias, size_t strBias, int hasBias,
              float* __restrict__ C, size_t strC,
              int M, int N, int K, int act,
              const float* __restrict__ gnoise, const int* __restrict__ gseeds) {
    constexpr int BM = 128, BK = 16;
    constexpr int MT = WM / 16, NT = WN / 8;
    constexpr int WARPS_M = BM / WM;
    constexpr int NTH = 32 * WARPS_M * (BN / WN);
    constexpr int AGRP = 132;                      // words per 16-row x 8-k group (padded)
    constexpr int BGRP = 68;                       // words per 8-k x 8-col group (padded)
    constexpr int AWORDS = (BM / 16) * (BK / 8) * AGRP;
    constexpr int BWORDS = (BK / 8) * (BN / 8) * BGRP;
    constexpr int A4 = BM * BK / 4 / NTH;          // float4 A loads per thread
    constexpr int B4 = BK * BN / 4 / NTH;          // float4 B loads per thread

    __shared__ uint32_t As[2][AWORDS];
    __shared__ uint32_t Bs[2][BWORDS];

    int tid = threadIdx.x, lane = tid & 31, wid = tid >> 5;
    int g = lane >> 2, t4 = lane & 3;
    int wm = (wid % WARPS_M) * WM;
    int wn = (wid / WARPS_M) * WN;

    int p = blockIdx.z;
    A += (size_t)p * strA;
    W += (size_t)p * strW;
    C += (size_t)p * strC;
    const float* bp = hasBias ? (bias + (size_t)p * strBias) : nullptr;

    int row0 = blockIdx.y * BM, col0 = blockIdx.x * BN;

    float acc[MT][NT][4];
#pragma unroll
    for (int mt = 0; mt < MT; mt++)
#pragma unroll
        for (int nt = 0; nt < NT; nt++)
#pragma unroll
            for (int i = 0; i < 4; i++) acc[mt][nt][i] = 0.f;

    float4 va[A4], vb[B4];

    auto ldg_tile = [&](int kt) {
#pragma unroll
        for (int i = 0; i < A4; i++) {
            int idx = tid + i * NTH;
            int r = idx >> 2;
            int c4 = (idx & 3) * 4;
            int gr = row0 + r;
            va[i] = (gr < M) ? *reinterpret_cast<const float4*>(&A[(size_t)gr * K + kt + c4])
                             : make_float4(0.f, 0.f, 0.f, 0.f);
        }
#pragma unroll
        for (int i = 0; i < B4; i++) {
            int idx = tid + i * NTH;
            int r = idx / (BN / 4);
            int c4 = (idx % (BN / 4)) * 4;
            int gc = col0 + c4;
            vb[i] = (gc < N) ? *reinterpret_cast<const float4*>(&W[(size_t)(kt + r) * N + gc])
                             : make_float4(0.f, 0.f, 0.f, 0.f);
        }
    };
    auto sts_tile = [&](int buf) {
#pragma unroll
        for (int i = 0; i < A4; i++) {
            int idx = tid + i * NTH;
            int r = idx >> 2;
            int c4 = (idx & 3) * 4;
            int grp = ((r >> 4) * (BK / 8) + (c4 >> 3)) * AGRP;
            int reg = ((r >> 3) & 1) + (((c4 >> 2) & 1) << 1);
            int gg = r & 7;
            float f[4] = {va[i].x, va[i].y, va[i].z, va[i].w};
#pragma unroll
            for (int j = 0; j < 4; j++)
                As[buf][grp + (gg * 4 + j) * 4 + reg] = f2tf(f[j]);
        }
#pragma unroll
        for (int i = 0; i < B4; i++) {
            int idx = tid + i * NTH;
            int k = idx / (BN / 4);
            int c4 = (idx % (BN / 4)) * 4;
            int grp = ((k >> 3) * (BN / 8) + (c4 >> 3)) * BGRP;
            int reg = (k >> 2) & 1;
            int tt = k & 3;
            float f[4] = {vb[i].x, vb[i].y, vb[i].z, vb[i].w};
#pragma unroll
            for (int j = 0; j < 4; j++)
                Bs[buf][grp + (((c4 & 7) + j) * 4 + tt) * 2 + reg] = f2tf(f[j]);
        }
    };

    int ntiles = K / BK;
    ldg_tile(0);
    sts_tile(0);
    __syncthreads();
    int cur = 0;

    for (int kt = 0; kt < ntiles; kt++) {
        if (kt + 1 < ntiles) ldg_tile((kt + 1) * BK);
#pragma unroll
        for (int ksb = 0; ksb < BK / 8; ksb++) {
            uint4 af[MT];
            uint2 bf[NT];
#pragma unroll
            for (int mt = 0; mt < MT; mt++)
                af[mt] = *reinterpret_cast<const uint4*>(
                    &As[cur][(((wm >> 4) + mt) * (BK / 8) + ksb) * AGRP + lane * 4]);
#pragma unroll
            for (int nt = 0; nt < NT; nt++)
                bf[nt] = *reinterpret_cast<const uint2*>(
                    &Bs[cur][(ksb * (BN / 8) + (wn >> 3) + nt) * BGRP + lane * 2]);
#pragma unroll
            for (int mt = 0; mt < MT; mt++)
#pragma unroll
                for (int nt = 0; nt < NT; nt++)
                    mma_tf32(acc[mt][nt], reinterpret_cast<const uint32_t*>(&af[mt]),
                             reinterpret_cast<const uint32_t*>(&bf[nt]));
        }
        if (kt + 1 < ntiles) {
            sts_tile(cur ^ 1);
            __syncthreads();
            cur ^= 1;
        }
    }

    // epilogue
#pragma unroll
    for (int mt = 0; mt < MT; mt++) {
#pragma unroll
        for (int nt = 0; nt < NT; nt++) {
            int gc = col0 + wn + nt * 8 + t4 * 2;
            if (gc >= N) continue;
            float bias0 = bp ? bp[gc] : 0.f;
            float bias1 = bp ? bp[gc + 1] : 0.f;
#pragma unroll
            for (int h = 0; h < 2; h++) {
                int gr = row0 + wm + mt * 16 + g + h * 8;
                if (gr >= M) continue;
                float v0 = acc[mt][nt][2 * h + 0] + bias0;
                float v1 = acc[mt][nt][2 * h + 1] + bias1;
                if (act == 1)      { v0 = fmaxf(v0, 0.f); v1 = fmaxf(v1, 0.f); }
                else if (act == 2) { v0 = (v0 > 0.f) ? v0 : 0.01f * v0;
                                     v1 = (v1 > 0.f) ? v1 : 0.01f * v1; }
                else if (act == 3) { v0 = tanhf(v0); v1 = tanhf(v1); }
                if (gnoise) {
                    const float* np = &gnoise[(size_t)gseeds[gr] * 64 + gc];
                    v0 += np[0];
                    v1 += np[1];
                }
                *reinterpret_cast<float2*>(&C[(size_t)gr * N + gc]) = make_float2(v0, v1);
            }
        }
    }
}

// ------------------------- launcher -------------------------
extern "C" void kernel_launch(void* const* d_in, const int* in_sizes, int n_in,
                              void* d_out, int out_size) {
    (void)in_sizes; (void)n_in; (void)out_size;
    const float* x     = (const float*)d_in[0];
    const int*   edges = (const int*)d_in[1];
    const int*   seeds = (const int*)d_in[2];
    const float* noise = (const float*)d_in[3];
    const float* V1    = (const float*)d_in[4];
    const float* C1    = (const float*)d_in[5];
    const float* V2    = (const float*)d_in[6];
    const float* C2    = (const float*)d_in[7];
    const float* W_lin = (const float*)d_in[8];
    const float* b_lin = (const float*)d_in[9];
    const float* Wd1   = (const float*)d_in[10];
    const float* bd1   = (const float*)d_in[11];
    const float* Wd2   = (const float*)d_in[12];
    const float* bd2   = (const float*)d_in[13];
    const float* Wd3   = (const float*)d_in[14];
    const float* bd3   = (const float*)d_in[15];
    const float* Wf1   = (const float*)d_in[16];
    const float* bf1   = (const float*)d_in[17];
    const float* Wf2   = (const float*)d_in[18];
    const float* bf2   = (const float*)d_in[19];
    const float* Wf3   = (const float*)d_in[20];
    const float* bf3   = (const float*)d_in[21];
    float* out = (float*)d_out;

    void *pDeg, *pIs, *pNeed, *pCnt, *pBcat, *pH1, *pSA, *pH2, *pHs, *pD1, *pD2, *pF1, *pF2;
    cudaGetSymbolAddress(&pDeg, g_deg);
    cudaGetSymbolAddress(&pIs, g_isseed);
    cudaGetSymbolAddress(&pNeed, g_need);
    cudaGetSymbolAddress(&pCnt, g_cnt);
    cudaGetSymbolAddress(&pBcat, g_Bcat);
    cudaGetSymbolAddress(&pH1, g_h1);
    cudaGetSymbolAddress(&pSA, g_sA);
    cudaGetSymbolAddress(&pH2, g_h2);
    cudaGetSymbolAddress(&pHs, g_hs);
    cudaGetSymbolAddress(&pD1, g_D1);
    cudaGetSymbolAddress(&pD2, g_D2);
    cudaGetSymbolAddress(&pF1, g_F1);
    cudaGetSymbolAddress(&pF2, g_F2);
    float* dBcat = (float*)pBcat;
    float* dH1   = (float*)pH1;
    float* dSA   = (float*)pSA;
    float* dH2   = (float*)pH2;
    float* dHs   = (float*)pHs;
    float* dD1   = (float*)pD1;
    float* dD2   = (float*)pD2;
    float* dF1   = (float*)pF1;
    float* dF2   = (float*)pF2;

    // zero small accumulators + flags (A zeroed selectively after need[] is known)
    cudaMemsetAsync(pDeg, 0, sizeof(float) * RR * NN);
    cudaMemsetAsync(pIs, 0, NN);
    cudaMemsetAsync(pNeed, 0, NN);
    cudaMemsetAsync(pCnt, 0, sizeof(int) * RR);

    const int scatterBlocks = (RR * EE * 16 + 255) / 256;

    k_seedflag<<<(SS + 255) / 256, 256>>>(seeds);
    k_edgepass<<<(RR * EE + 255) / 256, 256>>>(edges);
    k_invdeg<<<(RR * NN + 255) / 256, 256>>>();

    // ---- conv layer 1 (restricted to sources of seed-destined edges) ----
    k_zeroAneed<<<(NN * 16 + 255) / 256, 256>>>();
    k_scatterA<<<scatterBlocks, 256>>>(x, edges);
    k_combine1<<<(NN * 16 + 255) / 256, 256>>>(C1);
    mma_gemm<64, 32, 32, 1><<<dim3(1, (NN + 127) / 128, 1), 256>>>(
        dBcat, 0, V1, 0, nullptr, 0, 0, dH1, 0, NN, 64, 128, 1, nullptr, nullptr);

    // ---- conv layer 2 (compacted seed-edge list, grid-stride) ----
    k_zeroAseed<<<(SS * RR * 16 + 255) / 256, 256>>>(seeds);
    k_scatterList<<<1024, 256>>>(dH1);
    k_combine2<<<(SS * 16 + 255) / 256, 256>>>(C2, seeds);
    mma_gemm<64, 32, 32, 1><<<dim3(1, SS / 128, 1), 256>>>(
        dSA, 0, V2, 0, nullptr, 0, 0, dH2, 0, SS, 64, 128, 1, nullptr, nullptr);

    // ---- linear + leaky + noise at seeds (noise fused into epilogue) ----
    mma_gemm<64, 32, 32, 1><<<dim3(1, SS / 128, 1), 256>>>(
        dH2, 0, W_lin, 0, b_lin, 0, 1, dHs, 0, SS, 64, 64, 2, noise, seeds);

    // ---- d branch ----
    mma_gemm<128, 64, 32, 1><<<dim3(2, SS / 128, PP), 256>>>(
        dHs, 0, Wd1, (size_t)64 * 256, bd1, 256, 1, dD1, (size_t)SS * 256, SS, 256, 64, 2,
        nullptr, nullptr);
    mma_gemm<64, 32, 32, 1><<<dim3(1, SS / 128, PP), 256>>>(
        dD1, (size_t)SS * 256, Wd2, (size_t)256 * 32, bd2, 32, 1, dD2, (size_t)SS * 32,
        SS, 32, 256, 2, nullptr, nullptr);
    k_d3<<<(PP * SS + 255) / 256, 256>>>(Wd3, bd3, out);

    // ---- f branch ----
    mma_gemm<128, 64, 32, 1><<<dim3(2, SS / 128, PP), 256>>>(
        dHs, 0, Wf1, (size_t)64 * 256, bf1, 256, 1, dF1, (size_t)SS * 256, SS, 256, 64, 1,
        nullptr, nullptr);
    mma_gemm<128, 64, 64, 2><<<dim3(16, SS / 128, PP), 128>>>(
        dF1, (size_t)SS * 256, Wf2, (size_t)256 * 2048, bf2, 2048, 1, dF2, (size_t)SS * 2048,
        SS, 2048, 256, 1, nullptr, nullptr);
    mma_gemm<128, 64, 64, 2><<<dim3(3, SS / 128, PP), 128>>>(
        dF2, (size_t)SS * 2048, Wf3, (size_t)2048 * 320, bf3, 320, 1, out + PP * SS,
        (size_t)SS * 320, SS, 320, 2048, 3, nullptr, nullptr);
}